// round 7
// baseline (speedup 1.0000x reference)
#include <cuda_runtime.h>
#include <math.h>

#define BB 2
#define HH 128
#define WW 128
#define CC 128
#define NBR 9
#define HID 128
#define TP 16                 // positions per CTA
#define MROWS (TP*NBR)        // 144 edge rows per CTA
#define ASTR 130              // smem row stride (floats), even for u64 loads, odd/32 residue for banks
#define BSTR 130

typedef unsigned long long u64;

// ---------------- device scratch (allocation-free rule: __device__ globals) ----------------
__device__ float g_norm[BB*HH*WW*CC];      // LN1 output, 16.8 MB
__device__ float g_W3[CC*384];             // [c2][ Pn_d(128) | Pn_r(128) | vW(128) ]
__device__ float g_Wc[CC*256];             // [c ][ Pc_d(128) | Pc_r(128) ]
__device__ float g_reld[NBR*HID];          // rel@W1d + b1 (drive)
__device__ float g_relr[NBR*HID];          // rel@W1d + b1 (resistance)

struct SmemLayout {
  float A[MROWS*ASTR];       // gathered nbhd tile, [m][k]
  float Bm[CC*BSTR];         // weight tile transposed, [j][k]
  float center[TP*CC];       // normalized center rows
  float cterm[2][TP*HID];    // center pre-activation terms (d, r)
  float drive[TP*NBR];
  float res[TP*NBR];
  float gate[TP*NBR];
  float gsum[TP];
  float msg[TP*CC];
};
#define SMEM_BYTES ((int)sizeof(SmemLayout))

// -------- packed fp32x2 FMA (sm_103a; doubles FFMA throughput; pair over K) --------
__device__ __forceinline__ u64 fma2(u64 a, u64 b, u64 c){
  u64 d;
  asm("fma.rn.f32x2 %0, %1, %2, %3;" : "=l"(d) : "l"(a), "l"(b), "l"(c));
  return d;
}
__device__ __forceinline__ float pairsum(u64 v){
  union { u64 u; float2 f; } cv; cv.u = v;
  return cv.f.x + cv.f.y;
}

// ---------------- weight preprocessing ----------------
__global__ void prep_kernel(const float* __restrict__ dW1, const float* __restrict__ rW1,
                            const float* __restrict__ vW,  const float* __restrict__ rel,
                            const float* __restrict__ db1, const float* __restrict__ rb1)
{
  int idx = blockIdx.x*blockDim.x + threadIdx.x;
  if (idx < CC*384){
    int k = idx / 384, j = idx - k*384;
    float v;
    if (j < 128)       v = dW1[(128+k)*HID + j]       - dW1[(256+k)*HID + j];
    else if (j < 256)  v = rW1[(128+k)*HID + (j-128)] - rW1[(256+k)*HID + (j-128)];
    else               v = vW[k*CC + (j-256)];
    g_W3[idx] = v;
    return;
  }
  idx -= CC*384;
  if (idx < CC*256){
    int k = idx / 256, j = idx - k*256;
    float v;
    if (j < 128) v = dW1[k*HID + j]       + dW1[(256+k)*HID + j];
    else         v = rW1[k*HID + (j-128)] + rW1[(256+k)*HID + (j-128)];
    g_Wc[idx] = v;
    return;
  }
  idx -= CC*256;
  if (idx < 2*NBR*HID){
    int which = idx / (NBR*HID);
    int r = idx - which*(NBR*HID);
    int n = r / HID, hcol = r - n*HID;
    const float* W1 = which ? rW1 : dW1;
    const float* bb = which ? rb1 : db1;
    float acc = bb[hcol];
    #pragma unroll
    for (int p = 0; p < 8; ++p) acc += rel[n*8+p] * W1[(384+p)*HID + hcol];
    if (which) g_relr[r] = acc; else g_reld[r] = acc;
  }
}

// ---------------- LN1 ----------------
__global__ void ln1_kernel(const float* __restrict__ tokens,
                           const float* __restrict__ g, const float* __restrict__ b)
{
  int warp = (blockIdx.x*blockDim.x + threadIdx.x) >> 5;
  int lane = threadIdx.x & 31;
  if (warp >= BB*HH*WW) return;
  const float4 v = ((const float4*)(tokens + (size_t)warp*CC))[lane];
  float s = v.x + v.y + v.z + v.w;
  #pragma unroll
  for (int o = 16; o; o >>= 1) s += __shfl_xor_sync(0xffffffffu, s, o);
  float mean = s * (1.f/128.f);
  float dx=v.x-mean, dy=v.y-mean, dz=v.z-mean, dw=v.w-mean;
  float q = dx*dx + dy*dy + dz*dz + dw*dw;
  #pragma unroll
  for (int o = 16; o; o >>= 1) q += __shfl_xor_sync(0xffffffffu, q, o);
  float rs = rsqrtf(q*(1.f/128.f) + 1e-5f);
  float4 gg = ((const float4*)g)[lane];
  float4 bb = ((const float4*)b)[lane];
  float4 o4 = make_float4(dx*rs*gg.x+bb.x, dy*rs*gg.y+bb.y, dz*rs*gg.z+bb.z, dw*rs*gg.w+bb.w);
  ((float4*)(g_norm + (size_t)warp*CC))[lane] = o4;
}

// ---------------- helpers for the main fused kernel ----------------
__device__ __forceinline__ void load_Bm(SmemLayout& S, const float* __restrict__ src,
                                        int srcStride, int srcOff, int t)
{
  // Bm[j][k] = src[k][srcOff + j]; coalesced global read, ~2-way smem write conflict
  #pragma unroll 4
  for (int it = 0; it < 32; ++it){
    int e = it*512 + t;
    int k = e >> 7, j = e & 127;
    S.Bm[j*BSTR + k] = src[k*srcStride + srcOff + j];
  }
}

// 9-row x 4-col register tile GEMM: rows m = ty*9+i, cols j = tx + jj*32, K=128 paired
__device__ __forceinline__ void gemm_row9(const SmemLayout& S, int ty, int tx, float res[NBR][4])
{
  u64 acc[NBR][4];
  #pragma unroll
  for (int i = 0; i < NBR; ++i)
    #pragma unroll
    for (int jj = 0; jj < 4; ++jj) acc[i][jj] = 0ull;
  const float* ap = &S.A[(ty*9)*ASTR];
  const float* bp = &S.Bm[tx*BSTR];
  #pragma unroll 4
  for (int k = 0; k < CC; k += 2){
    u64 b2[4];
    #pragma unroll
    for (int jj = 0; jj < 4; ++jj)
      b2[jj] = *reinterpret_cast<const u64*>(bp + (jj*32)*BSTR + k);
    #pragma unroll
    for (int i = 0; i < NBR; ++i){
      u64 a2 = *reinterpret_cast<const u64*>(ap + i*ASTR + k);
      #pragma unroll
      for (int jj = 0; jj < 4; ++jj)
        acc[i][jj] = fma2(a2, b2[jj], acc[i][jj]);
    }
  }
  #pragma unroll
  for (int i = 0; i < NBR; ++i)
    #pragma unroll
    for (int jj = 0; jj < 4; ++jj) res[i][jj] = pairsum(acc[i][jj]);
}

// 1-row x 4-col GEMM (center term / output projection)
__device__ __forceinline__ void gemm_row1(const SmemLayout& S, const float* __restrict__ ap,
                                          int tx, float res[4])
{
  u64 acc[4] = {0ull,0ull,0ull,0ull};
  const float* bp = &S.Bm[tx*BSTR];
  #pragma unroll 8
  for (int k = 0; k < CC; k += 2){
    u64 a2 = *reinterpret_cast<const u64*>(ap + k);
    #pragma unroll
    for (int jj = 0; jj < 4; ++jj)
      acc[jj] = fma2(a2, *reinterpret_cast<const u64*>(bp + (jj*32)*BSTR + k), acc[jj]);
  }
  #pragma unroll
  for (int jj = 0; jj < 4; ++jj) res[jj] = pairsum(acc[jj]);
}

// ---------------- main fused kernel: one CTA = 16 positions of one (b, h) row ----------------
__global__ void __launch_bounds__(512, 1) eml_main(
    const float* __restrict__ tokens,
    const float* __restrict__ dW2, const float* __restrict__ db2,
    const float* __restrict__ rW2, const float* __restrict__ rb2,
    const float* __restrict__ vb,  const float* __restrict__ oW,
    const float* __restrict__ ob,  const float* __restrict__ ln2g,
    const float* __restrict__ ln2b,
    const float* __restrict__ gamp, const float* __restrict__ lamp,
    const float* __restrict__ biasp,
    float* __restrict__ out)
{
  extern __shared__ float smraw[];
  SmemLayout& S = *reinterpret_cast<SmemLayout*>(smraw);
  const int t  = threadIdx.x;
  const int ty = t >> 5;      // position within tile (0..15)
  const int tx = t & 31;      // column lane
  const int w0 = blockIdx.x * TP;
  const int h  = blockIdx.y;
  const int b  = blockIdx.z;

  // ---- Stage A: gather 9 shifted rows per position, scatter through the torch-reshape bijection ----
  #pragma unroll 2
  for (int it = 0; it < 36; ++it){          // 144 rows * 128 ch / 512 threads
    int e  = it*512 + t;
    int ch = e & 127;
    int ps = e >> 7;
    int p  = ps / 9, s = ps - p*9;
    int hh = h + (s/3) - 1;
    int ww = w0 + p + (s - (s/3)*3) - 1;
    float v = 0.f;
    if ((unsigned)hh < HH && (unsigned)ww < WW)
      v = g_norm[(((b*HH + hh)*WW + ww) << 7) + ch];
    int q = ch*9 + s;                        // (s,ch) -> (n,c2)
    S.A[(p*9 + (q >> 7))*ASTR + (q & 127)] = v;
  }
  for (int it = 0; it < 4; ++it){
    int e = it*512 + t;
    int p = e >> 7, ch = e & 127;
    S.center[e] = g_norm[(((b*HH + h)*WW + (w0+p)) << 7) + ch];
  }
  __syncthreads();

  // ---- Center pre-activation terms (per position, not per edge) ----
  for (int half = 0; half < 2; ++half){
    load_Bm(S, g_Wc, 256, half*128, t);
    __syncthreads();
    float cres[4];
    gemm_row1(S, &S.center[ty*CC], tx, cres);
    #pragma unroll
    for (int jj = 0; jj < 4; ++jj)
      S.cterm[half][ty*HID + tx + jj*32] = cres[jj];
    __syncthreads();
  }

  // ---- Drive / Resistance: nbhd-term GEMM + GELU + dot(W2) + cross-lane reduce ----
  for (int chunk = 0; chunk < 2; ++chunk){
    load_Bm(S, g_W3, 384, chunk*128, t);
    __syncthreads();
    float res9[NBR][4];
    gemm_row9(S, ty, tx, res9);

    const float* W2   = chunk ? rW2 : dW2;
    const float* relb = chunk ? g_relr : g_reld;
    float w2v[4];
    #pragma unroll
    for (int jj = 0; jj < 4; ++jj) w2v[jj] = W2[tx + jj*32];
    const float* ct = &S.cterm[chunk][ty*HID];

    #pragma unroll
    for (int i = 0; i < NBR; ++i){
      float sum = 0.f;
      #pragma unroll
      for (int jj = 0; jj < 4; ++jj){
        int hcol = tx + jj*32;
        float x = res9[i][jj] + ct[hcol] + relb[i*HID + hcol];
        float gel = 0.5f * x * (1.f + erff(x * 0.70710678118654752f));
        sum += gel * w2v[jj];
      }
      #pragma unroll
      for (int o = 16; o; o >>= 1) sum += __shfl_xor_sync(0xffffffffu, sum, o);
      if (tx == 0){
        float b2s = chunk ? rb2[0] : db2[0];
        (chunk ? S.res : S.drive)[ty*NBR + i] = sum + b2s;
      }
    }
    __syncthreads();
  }

  // ---- EML gate ----
  if (t < TP*NBR){
    float d = S.drive[t], r = S.res[t];
    float sp = (r > 20.f) ? r : log1pf(expf(r));
    float e = (gamp[0] * d) / (lamp[0] * sp + 1e-6f) + biasp[0];
    e = fminf(3.f, fmaxf(-3.f, e));
    S.gate[t] = 1.f / (1.f + expf(-e));
  }
  __syncthreads();
  if (t < TP){
    float s = 0.f;
    #pragma unroll
    for (int n = 0; n < NBR; ++n) s += S.gate[t*NBR + n];
    S.gsum[t] = s;
  }
  __syncthreads();

  // ---- Values GEMM + gated message ----
  {
    load_Bm(S, g_W3, 384, 256, t);
    __syncthreads();
    float val9[NBR][4];
    gemm_row9(S, ty, tx, val9);

    float gsum = S.gsum[ty];
    float inv  = 1.f / fmaxf(gsum, 1e-6f);
    float gt[NBR];
    #pragma unroll
    for (int i = 0; i < NBR; ++i) gt[i] = S.gate[ty*NBR + i];
    #pragma unroll
    for (int jj = 0; jj < 4; ++jj){
      int c = tx + jj*32;
      float acv = 0.f;
      #pragma unroll
      for (int i = 0; i < NBR; ++i) acv += gt[i] * val9[i][jj];
      S.msg[ty*CC + c] = (acv + gsum * vb[c]) * inv;
    }
    __syncthreads();
  }

  // ---- Output projection + residual + LN2 ----
  {
    load_Bm(S, oW, CC, 0, t);
    __syncthreads();
    float upd[4];
    gemm_row1(S, &S.msg[ty*CC], tx, upd);

    const int base = (((b*HH + h)*WW + (w0 + ty)) << 7);
    float u[4], ssum = 0.f, ssq = 0.f;
    #pragma unroll
    for (int jj = 0; jj < 4; ++jj){
      int c = tx + jj*32;
      u[jj] = tokens[base + c] + upd[jj] + ob[c];
      ssum += u[jj];
      ssq  += u[jj]*u[jj];
    }
    #pragma unroll
    for (int o = 16; o; o >>= 1){
      ssum += __shfl_xor_sync(0xffffffffu, ssum, o);
      ssq  += __shfl_xor_sync(0xffffffffu, ssq,  o);
    }
    float mean = ssum * (1.f/128.f);
    float var  = ssq * (1.f/128.f) - mean*mean;
    float rs   = rsqrtf(var + 1e-5f);
    #pragma unroll
    for (int jj = 0; jj < 4; ++jj){
      int c = tx + jj*32;
      out[base + c] = (u[jj] - mean) * rs * ln2g[c] + ln2b[c];
    }
  }
}

// ---------------- launcher ----------------
extern "C" void kernel_launch(void* const* d_in, const int* in_sizes, int n_in,
                              void* d_out, int out_size)
{
  const float* tokens = (const float*)d_in[0];
  const float* ln1g   = (const float*)d_in[1];
  const float* ln1b   = (const float*)d_in[2];
  const float* ln2g   = (const float*)d_in[3];
  const float* ln2b   = (const float*)d_in[4];
  const float* rel    = (const float*)d_in[5];
  const float* dW1    = (const float*)d_in[6];
  const float* db1    = (const float*)d_in[7];
  const float* dW2    = (const float*)d_in[8];
  const float* db2    = (const float*)d_in[9];
  const float* rW1    = (const float*)d_in[10];
  const float* rb1    = (const float*)d_in[11];
  const float* rW2    = (const float*)d_in[12];
  const float* rb2    = (const float*)d_in[13];
  const float* vW     = (const float*)d_in[14];
  const float* vb     = (const float*)d_in[15];
  const float* oW     = (const float*)d_in[16];
  const float* ob     = (const float*)d_in[17];
  const float* gam    = (const float*)d_in[18];
  const float* lam    = (const float*)d_in[19];
  const float* bias   = (const float*)d_in[20];

  cudaFuncSetAttribute(eml_main, cudaFuncAttributeMaxDynamicSharedMemorySize, SMEM_BYTES);

  {
    int total = CC*384 + CC*256 + 2*NBR*HID;
    prep_kernel<<<(total + 255)/256, 256>>>(dW1, rW1, vW, rel, db1, rb1);
  }
  ln1_kernel<<<(BB*HH*WW)/16, 512>>>(tokens, ln1g, ln1b);

  dim3 grid(WW/TP, HH, BB);
  eml_main<<<grid, 512, SMEM_BYTES>>>(tokens, dW2, db2, rW2, rb2, vb, oW, ob,
                                      ln2g, ln2b, gam, lam, bias, (float*)d_out);
}

// round 10
// speedup vs baseline: 1.6879x; 1.6879x over previous
#include <cuda_runtime.h>
#include <cuda_bf16.h>
#include <math.h>
#include <stdint.h>

#define TOTP 32768
#define TP 16
#define NCTA (TOTP/TP)          // 2048
#define NTH 288                 // 9 warps
#define ROWS 144                // TP*9
#define AST 264                 // bf16 row stride (528B -> conflict-free ldmatrix)
#define OFF_B 76032             // A: 144*264*2
#define OFF_TAB 143616          // + B: 128*264*2
#define T_RELBD 0
#define T_RELBR 1188
#define T_W2D 2376
#define T_W2R 2504
#define T_VB 2632
#define T_DRV 2760
#define T_RES 2904
#define T_GAT 3048
#define T_GSM 3192
#define T_MSG 3208
#define SMEM_TOTAL (OFF_TAB + 5320*4)

__device__ __align__(16) __nv_bfloat16 g_normbf[(size_t)TOTP*128];
__device__ __align__(16) __nv_bfloat16 g_Bd[128*AST];
__device__ __align__(16) __nv_bfloat16 g_Br[128*AST];
__device__ __align__(16) __nv_bfloat16 g_Bv[128*AST];
__device__ float g_reld[1152];
__device__ float g_relr[1152];

__device__ __forceinline__ uint32_t smem_u32(const void* p){
  uint32_t a;
  asm("{ .reg .u64 t; cvta.to.shared.u64 t, %1; cvt.u32.u64 %0, t; }" : "=r"(a) : "l"(p));
  return a;
}
__device__ __forceinline__ void ldm4(uint32_t& r0, uint32_t& r1, uint32_t& r2, uint32_t& r3, uint32_t a){
  asm volatile("ldmatrix.sync.aligned.m8n8.x4.shared.b16 {%0,%1,%2,%3}, [%4];"
               : "=r"(r0), "=r"(r1), "=r"(r2), "=r"(r3) : "r"(a));
}
__device__ __forceinline__ void mma16816(float* d, uint32_t a0, uint32_t a1, uint32_t a2, uint32_t a3,
                                         uint32_t b0, uint32_t b1){
  asm volatile("mma.sync.aligned.m16n8k16.row.col.f32.bf16.bf16.f32 "
               "{%0,%1,%2,%3},{%4,%5,%6,%7},{%8,%9},{%0,%1,%2,%3};"
               : "+f"(d[0]), "+f"(d[1]), "+f"(d[2]), "+f"(d[3])
               : "r"(a0), "r"(a1), "r"(a2), "r"(a3), "r"(b0), "r"(b1));
}
__device__ __forceinline__ void mma_tile(uint32_t aAddr, uint32_t bAddr, int ks, float (&d)[16][4]){
  #pragma unroll
  for (int nt = 0; nt < 16; ++nt){ d[nt][0]=0.f; d[nt][1]=0.f; d[nt][2]=0.f; d[nt][3]=0.f; }
  for (int kb = 0; kb < ks; ++kb){
    uint32_t a0,a1,a2,a3;
    ldm4(a0,a1,a2,a3, aAddr + kb*32);
    #pragma unroll
    for (int jt = 0; jt < 8; ++jt){
      uint32_t b0,b1,b2,b3;
      ldm4(b0,b1,b2,b3, bAddr + jt*8448 + kb*32);
      mma16816(d[2*jt],   a0,a1,a2,a3, b0,b1);
      mma16816(d[2*jt+1], a0,a1,a2,a3, b2,b3);
    }
  }
}
__device__ __forceinline__ float gelu(float x){
  return 0.5f*x*(1.f + erff(x*0.70710678118654752f));
}

// ---------------- prep: folded weights (plain padded [j][k] bf16) + rel biases ----------------
__global__ void prep_kernel(const float* __restrict__ dW1, const float* __restrict__ rW1,
                            const float* __restrict__ vW,  const float* __restrict__ rel,
                            const float* __restrict__ db1, const float* __restrict__ rb1)
{
  int idx = blockIdx.x*256 + threadIdx.x;
  if (idx < 32768){                       // Bd + Br, [j][k] k<256
    int j = idx >> 8, k = idx & 255;
    float vd, vr;
    if (k < 128){
      vd = dW1[(128+k)*128+j] - dW1[(256+k)*128+j];
      vr = rW1[(128+k)*128+j] - rW1[(256+k)*128+j];
    } else {
      vd = dW1[(k-128)*128+j] + dW1[(k+128)*128+j];
      vr = rW1[(k-128)*128+j] + rW1[(k+128)*128+j];
    }
    g_Bd[j*AST+k] = __float2bfloat16(vd);
    g_Br[j*AST+k] = __float2bfloat16(vr);
    return;
  }
  idx -= 32768;
  if (idx < 16384){                       // Bv
    int j = idx >> 7, k = idx & 127;
    g_Bv[j*AST+k] = __float2bfloat16(vW[k*128+j]);
    return;
  }
  idx -= 16384;
  if (idx < 2304){
    int wh = idx/1152, r = idx - wh*1152, n = r>>7, j = r&127;
    const float* W1 = wh ? rW1 : dW1;
    float a = (wh ? rb1 : db1)[j];
    #pragma unroll
    for (int p = 0; p < 8; ++p) a += rel[n*8+p] * W1[(384+p)*128+j];
    (wh ? g_relr : g_reld)[r] = a;
  }
}

// ---------------- LN1 -> bf16 ----------------
__global__ void ln1_kernel(const float* __restrict__ tok, const float* __restrict__ g,
                           const float* __restrict__ b)
{
  int warp = (blockIdx.x*blockDim.x + threadIdx.x) >> 5, lane = threadIdx.x & 31;
  if (warp >= TOTP) return;
  float4 v = ((const float4*)(tok + (size_t)warp*128))[lane];
  float s = v.x+v.y+v.z+v.w;
  #pragma unroll
  for (int o=16;o;o>>=1) s += __shfl_xor_sync(~0u, s, o);
  float mean = s*(1.f/128.f);
  float dx=v.x-mean, dy=v.y-mean, dz=v.z-mean, dw=v.w-mean;
  float q = dx*dx+dy*dy+dz*dz+dw*dw;
  #pragma unroll
  for (int o=16;o;o>>=1) q += __shfl_xor_sync(~0u, q, o);
  float rs = rsqrtf(q*(1.f/128.f) + 1e-5f);
  float4 gg = ((const float4*)g)[lane], bb = ((const float4*)b)[lane];
  __nv_bfloat162 lo = __floats2bfloat162_rn(dx*rs*gg.x+bb.x, dy*rs*gg.y+bb.y);
  __nv_bfloat162 hi = __floats2bfloat162_rn(dz*rs*gg.z+bb.z, dw*rs*gg.w+bb.w);
  uint2 pk; pk.x = *(uint32_t*)&lo; pk.y = *(uint32_t*)&hi;
  ((uint2*)(g_normbf + (size_t)warp*128))[lane] = pk;
}

// ---------------- main ----------------
__global__ void __launch_bounds__(NTH,1) eml_main(
    const float* __restrict__ tokens, const float* __restrict__ dW2,
    const float* __restrict__ db2, const float* __restrict__ rW2,
    const float* __restrict__ rb2, const float* __restrict__ vb,
    const float* __restrict__ ob, const float* __restrict__ ln2g,
    const float* __restrict__ ln2b, const float* __restrict__ oW,
    const float* __restrict__ gam, const float* __restrict__ lam,
    const float* __restrict__ bia, float* __restrict__ out)
{
  extern __shared__ __align__(16) unsigned char sm[];
  const uint32_t smb = smem_u32(sm);
  float* TAB = (float*)(sm + OFF_TAB);
  const int t = threadIdx.x, w = t>>5, lane = t&31;
  const int l0 = blockIdx.x * TP;

  // ---- stage 1: gather A (scrambled nbhd k<128, center k>=128), copy Bd, tables ----
  for (int e = t; e < ROWS*128; e += NTH){   // scrambled nbhd
    int ch = e & 127, ps = e >> 7;
    int p = ps/9, s = ps - 9*p;
    int l = l0 + p;
    int h = (l>>7)&127, wp = l&127;
    int dh = s/3 - 1, dw = (s - 3*(s/3)) - 1;
    uint16_t val = 0;
    if ((unsigned)(h+dh) < 128u && (unsigned)(wp+dw) < 128u)
      val = *(const uint16_t*)(g_normbf + (((size_t)l + (dh<<7) + dw)<<7) + ch);
    int q = ch*9 + s;
    *(uint16_t*)(sm + (p*9 + (q>>7))*AST*2 + ((q&127)<<1)) = val;
  }
  for (int e = t; e < ROWS*16; e += NTH){    // center block as uint4
    int m = e >> 4, q16 = e & 15;
    int p = m/9;
    *(uint4*)(sm + m*AST*2 + 256 + q16*16) =
      *(const uint4*)(g_normbf + ((size_t)(l0+p)<<7) + q16*8);
  }
  for (int e = t; e < 4224; e += NTH)
    ((uint4*)(sm+OFF_B))[e] = ((const uint4*)g_Bd)[e];
  for (int e = t; e < 1152; e += NTH){
    int n = e>>7, j = e&127;
    TAB[T_RELBD + n*132 + j] = g_reld[e];
    TAB[T_RELBR + n*132 + j] = g_relr[e];
  }
  if (t < 128){ TAB[T_W2D+t]=dW2[t]; TAB[T_W2R+t]=rW2[t]; TAB[T_VB+t]=vb[t]; }
  __syncthreads();

  const uint32_t aAddr = smb + ((16*w + (lane&15))*AST + ((lane>>4)<<3))*2;
  const uint32_t bAddr = smb + OFF_B + ((((lane>>4)<<3)+(lane&7))*AST + (((lane>>3)&1)<<3))*2;
  const int r0 = 16*w + (lane>>2), r1 = r0 + 8;
  const int n0 = r0 - 9*(r0/9), n1 = r1 - 9*(r1/9);
  const int jb = (lane&3)<<1;
  float d[16][4];

  // ---- tile 0: drive (K=256) ----
  mma_tile(aAddr, bAddr, 16, d);
  {
    const float* rb0 = TAB + T_RELBD + n0*132;
    const float* rb1v = TAB + T_RELBD + n1*132;
    const float* w2 = TAB + T_W2D;
    float a0 = 0.f, a1 = 0.f;
    #pragma unroll
    for (int nt = 0; nt < 16; ++nt){
      int j = nt*8 + jb;
      a0 += gelu(d[nt][0] + rb0[j])*w2[j] + gelu(d[nt][1] + rb0[j+1])*w2[j+1];
      a1 += gelu(d[nt][2] + rb1v[j])*w2[j] + gelu(d[nt][3] + rb1v[j+1])*w2[j+1];
    }
    a0 += __shfl_xor_sync(~0u, a0, 1); a0 += __shfl_xor_sync(~0u, a0, 2);
    a1 += __shfl_xor_sync(~0u, a1, 1); a1 += __shfl_xor_sync(~0u, a1, 2);
    if ((lane&3) == 0){ TAB[T_DRV + r0] = a0; TAB[T_DRV + r1] = a1; }
  }
  __syncthreads();

  // ---- tile 1: resistance ----
  for (int e = t; e < 4224; e += NTH)
    ((uint4*)(sm+OFF_B))[e] = ((const uint4*)g_Br)[e];
  __syncthreads();
  mma_tile(aAddr, bAddr, 16, d);
  {
    const float* rb0 = TAB + T_RELBR + n0*132;
    const float* rb1v = TAB + T_RELBR + n1*132;
    const float* w2 = TAB + T_W2R;
    float a0 = 0.f, a1 = 0.f;
    #pragma unroll
    for (int nt = 0; nt < 16; ++nt){
      int j = nt*8 + jb;
      a0 += gelu(d[nt][0] + rb0[j])*w2[j] + gelu(d[nt][1] + rb0[j+1])*w2[j+1];
      a1 += gelu(d[nt][2] + rb1v[j])*w2[j] + gelu(d[nt][3] + rb1v[j+1])*w2[j+1];
    }
    a0 += __shfl_xor_sync(~0u, a0, 1); a0 += __shfl_xor_sync(~0u, a0, 2);
    a1 += __shfl_xor_sync(~0u, a1, 1); a1 += __shfl_xor_sync(~0u, a1, 2);
    if ((lane&3) == 0){ TAB[T_RES + r0] = a0; TAB[T_RES + r1] = a1; }
  }
  __syncthreads();

  // ---- gate + stage Bv ----
  for (int e = t; e < 4224; e += NTH)
    ((uint4*)(sm+OFF_B))[e] = ((const uint4*)g_Bv)[e];
  if (t < ROWS){
    float dv = TAB[T_DRV+t] + db2[0], rv = TAB[T_RES+t] + rb2[0];
    float sp = (rv > 20.f) ? rv : log1pf(expf(rv));
    float e = (gam[0]*dv) / (lam[0]*sp + 1e-6f) + bia[0];
    e = fminf(3.f, fmaxf(-3.f, e));
    TAB[T_GAT+t] = 1.f / (1.f + expf(-e));
  }
  __syncthreads();

  // ---- tile 2: values (K=128); V overwrites own A rows (row footprints identical) ----
  mma_tile(aAddr, bAddr, 8, d);
  if (t < TP){
    float s = 0.f;
    #pragma unroll
    for (int n = 0; n < 9; ++n) s += TAB[T_GAT + t*9 + n];
    TAB[T_GSM+t] = s;
  }
  {
    float* V = (float*)sm;                  // [144][132] fp32
    #pragma unroll
    for (int nt = 0; nt < 16; ++nt){
      int j = nt*8 + jb;
      *(float2*)&V[r0*132 + j] = make_float2(d[nt][0], d[nt][1]);
      *(float2*)&V[r1*132 + j] = make_float2(d[nt][2], d[nt][3]);
    }
  }
  __syncthreads();

  // ---- message + stage oW (B region free) ----
  for (int e = t; e < 4096; e += NTH)
    ((uint4*)(sm+OFF_B))[e] = ((const uint4*)oW)[e];      // fp32 [c][d]
  {
    const float* V = (const float*)sm;
    for (int e = t; e < TP*128; e += NTH){
      int p = e>>7, c = e&127, mb = p*9;
      float s = 0.f;
      #pragma unroll
      for (int n = 0; n < 9; ++n) s += TAB[T_GAT + mb + n] * V[(mb+n)*132 + c];
      float gs = TAB[T_GSM + p];
      TAB[T_MSG + p*132 + c] = (s + gs*TAB[T_VB+c]) / fmaxf(gs, 1e-6f);
    }
  }
  __syncthreads();

  // ---- projection + residual + LN2 + store: one warp per position ----
  const float4* oWs4 = (const float4*)(sm + OFF_B);
  for (int p = w; p < TP; p += 9){
    int l = l0 + p;
    const float* msg = TAB + T_MSG + p*132;
    float4 acc = make_float4(0.f, 0.f, 0.f, 0.f);
    #pragma unroll 4
    for (int c = 0; c < 128; ++c){
      float mv = msg[c];
      float4 wv = oWs4[c*32 + lane];
      acc.x += wv.x*mv; acc.y += wv.y*mv; acc.z += wv.z*mv; acc.w += wv.w*mv;
    }
    size_t base4 = ((size_t)l << 5);
    float4 tk = ((const float4*)tokens)[base4 + lane];
    float4 obv = ((const float4*)ob)[lane];
    float u0 = tk.x+acc.x+obv.x, u1 = tk.y+acc.y+obv.y;
    float u2 = tk.z+acc.z+obv.z, u3 = tk.w+acc.w+obv.w;
    float ss = u0+u1+u2+u3, sq = u0*u0+u1*u1+u2*u2+u3*u3;
    #pragma unroll
    for (int o=16;o;o>>=1){ ss += __shfl_xor_sync(~0u,ss,o); sq += __shfl_xor_sync(~0u,sq,o); }
    float mean = ss*(1.f/128.f);
    float rs = rsqrtf(sq*(1.f/128.f) - mean*mean + 1e-5f);
    float4 gg = ((const float4*)ln2g)[lane], bb = ((const float4*)ln2b)[lane];
    ((float4*)out)[base4 + lane] = make_float4(
      (u0-mean)*rs*gg.x+bb.x, (u1-mean)*rs*gg.y+bb.y,
      (u2-mean)*rs*gg.z+bb.z, (u3-mean)*rs*gg.w+bb.w);
  }
}

extern "C" void kernel_launch(void* const* d_in, const int* in_sizes, int n_in,
                              void* d_out, int out_size)
{
  const float* tokens = (const float*)d_in[0];
  const float* ln1g = (const float*)d_in[1];
  const float* ln1b = (const float*)d_in[2];
  const float* ln2g = (const float*)d_in[3];
  const float* ln2b = (const float*)d_in[4];
  const float* rel  = (const float*)d_in[5];
  const float* dW1  = (const float*)d_in[6];
  const float* db1  = (const float*)d_in[7];
  const float* dW2  = (const float*)d_in[8];
  const float* db2  = (const float*)d_in[9];
  const float* rW1  = (const float*)d_in[10];
  const float* rb1  = (const float*)d_in[11];
  const float* rW2  = (const float*)d_in[12];
  const float* rb2  = (const float*)d_in[13];
  const float* vW   = (const float*)d_in[14];
  const float* vb   = (const float*)d_in[15];
  const float* oW   = (const float*)d_in[16];
  const float* ob   = (const float*)d_in[17];
  const float* gam  = (const float*)d_in[18];
  const float* lam  = (const float*)d_in[19];
  const float* bia  = (const float*)d_in[20];

  cudaFuncSetAttribute(eml_main, cudaFuncAttributeMaxDynamicSharedMemorySize, SMEM_TOTAL);
  prep_kernel<<<(51456 + 255)/256, 256>>>(dW1, rW1, vW, rel, db1, rb1);
  ln1_kernel<<<TOTP/16, 512>>>(tokens, ln1g, ln1b);
  eml_main<<<NCTA, NTH, SMEM_TOTAL>>>(tokens, dW2, db2, rW2, rb2, vb, ob,
                                      ln2g, ln2b, oW, gam, lam, bia, (float*)d_out);
}

// round 14
// speedup vs baseline: 3.0233x; 1.7912x over previous
#include <cuda_runtime.h>
#include <cuda_bf16.h>
#include <math.h>
#include <stdint.h>

#define TOTP 32768
#define TP 16
#define NTILES (TOTP/TP)        // 2048
#define GRID 148
#define NTH 288                 // 9 warps
#define ROWS 144
#define AST 264                 // bf16 row stride
#define OFF_B 76032             // A: 144*264*2
#define OFF_TAB 211200          // B: 256*264*2 = 135168
#define T_RELB 0
#define T_W2D 2304
#define T_W2R 2432
#define T_BO 2560
#define T_LN2G 2688
#define T_LN2B 2816
#define T_DRV 2944
#define T_RES 3088
#define T_GAT 3232
#define T_GSM 3376
#define SMEM_TOTAL (OFF_TAB + 3392*4)   // 224768

__device__ __align__(16) __nv_bfloat16 g_normbf[(size_t)TOTP*128];
__device__ __align__(16) __nv_bfloat16 g_B[256*AST];   // [j][k]: j<128 drive, j>=128 res
__device__ __align__(16) float g_Wvo[128*128];         // [c][o] = vW@oW
__device__ float g_bo[128];
__device__ float g_relb[2304];                         // drive 0..1151, res 1152..

__device__ __forceinline__ uint32_t smem_u32(const void* p){
  uint32_t a;
  asm("{ .reg .u64 t; cvta.to.shared.u64 t, %1; cvt.u32.u64 %0, t; }" : "=r"(a) : "l"(p));
  return a;
}
__device__ __forceinline__ void ldm4(uint32_t& r0, uint32_t& r1, uint32_t& r2, uint32_t& r3, uint32_t a){
  asm volatile("ldmatrix.sync.aligned.m8n8.x4.shared.b16 {%0,%1,%2,%3}, [%4];"
               : "=r"(r0), "=r"(r1), "=r"(r2), "=r"(r3) : "r"(a));
}
__device__ __forceinline__ void mma16816(float* d, uint32_t a0, uint32_t a1, uint32_t a2, uint32_t a3,
                                         uint32_t b0, uint32_t b1){
  asm volatile("mma.sync.aligned.m16n8k16.row.col.f32.bf16.bf16.f32 "
               "{%0,%1,%2,%3},{%4,%5,%6,%7},{%8,%9},{%0,%1,%2,%3};"
               : "+f"(d[0]), "+f"(d[1]), "+f"(d[2]), "+f"(d[3])
               : "r"(a0), "r"(a1), "r"(a2), "r"(a3), "r"(b0), "r"(b1));
}
__device__ __forceinline__ float gelu(float x){
  return 0.5f*x*(1.f + erff(x*0.70710678118654752f));
}

// ---------------- prep ----------------
__global__ void prep_kernel(const float* __restrict__ dW1, const float* __restrict__ rW1,
                            const float* __restrict__ vW,  const float* __restrict__ oW,
                            const float* __restrict__ vb,  const float* __restrict__ ob,
                            const float* __restrict__ rel,
                            const float* __restrict__ db1, const float* __restrict__ rb1)
{
  int idx = blockIdx.x*256 + threadIdx.x;
  if (idx < 65536){                        // B tile [j][k]
    int j = idx >> 8, k = idx & 255;
    const float* W = (j < 128) ? dW1 : rW1;
    int jc = j & 127;
    float v = (k < 128) ? (W[(128+k)*128+jc] - W[(256+k)*128+jc])
                        : (W[(k-128)*128+jc] + W[(k+128)*128+jc]);
    g_B[j*AST+k] = __float2bfloat16(v);
    return;
  }
  idx -= 65536;
  if (idx < 2304){                         // rel biases
    int wh = idx/1152, r = idx - wh*1152, n = r>>7, j = r&127;
    const float* W1 = wh ? rW1 : dW1;
    float a = (wh ? rb1 : db1)[j];
    #pragma unroll
    for (int p = 0; p < 8; ++p) a += rel[n*8+p] * W1[(384+p)*128+j];
    g_relb[idx] = a;
    return;
  }
  idx -= 2304;
  if (idx < 16384){                        // Wvo = vW@oW, [c][o]
    int c = idx >> 7, o = idx & 127;
    float s = 0.f;
    for (int d = 0; d < 128; ++d) s += vW[c*128+d] * oW[d*128+o];
    g_Wvo[idx] = s;
    return;
  }
  idx -= 16384;
  if (idx < 128){                          // bo = vb@oW + ob
    float s = ob[idx];
    for (int d = 0; d < 128; ++d) s += vb[d] * oW[d*128+idx];
    g_bo[idx] = s;
  }
}

// ---------------- LN1 -> bf16 ----------------
__global__ void ln1_kernel(const float* __restrict__ tok, const float* __restrict__ g,
                           const float* __restrict__ b)
{
  int warp = (blockIdx.x*blockDim.x + threadIdx.x) >> 5, lane = threadIdx.x & 31;
  if (warp >= TOTP) return;
  float4 v = ((const float4*)(tok + (size_t)warp*128))[lane];
  float s = v.x+v.y+v.z+v.w;
  #pragma unroll
  for (int o=16;o;o>>=1) s += __shfl_xor_sync(~0u, s, o);
  float mean = s*(1.f/128.f);
  float dx=v.x-mean, dy=v.y-mean, dz=v.z-mean, dw=v.w-mean;
  float q = dx*dx+dy*dy+dz*dz+dw*dw;
  #pragma unroll
  for (int o=16;o;o>>=1) q += __shfl_xor_sync(~0u, q, o);
  float rs = rsqrtf(q*(1.f/128.f) + 1e-5f);
  float4 gg = ((const float4*)g)[lane], bb = ((const float4*)b)[lane];
  __nv_bfloat162 lo = __floats2bfloat162_rn(dx*rs*gg.x+bb.x, dy*rs*gg.y+bb.y);
  __nv_bfloat162 hi = __floats2bfloat162_rn(dz*rs*gg.z+bb.z, dw*rs*gg.w+bb.w);
  uint2 pk; pk.x = *(uint32_t*)&lo; pk.y = *(uint32_t*)&hi;
  ((uint2*)(g_normbf + (size_t)warp*128))[lane] = pk;
}

// ---------------- main (persistent) ----------------
__global__ void __launch_bounds__(NTH,1) eml_main(
    const float* __restrict__ tokens, const float* __restrict__ dW2,
    const float* __restrict__ db2, const float* __restrict__ rW2,
    const float* __restrict__ rb2, const float* __restrict__ ln2g,
    const float* __restrict__ ln2b, const float* __restrict__ gam,
    const float* __restrict__ lam, const float* __restrict__ bia,
    float* __restrict__ out)
{
  extern __shared__ __align__(16) unsigned char sm[];
  const uint32_t smb = smem_u32(sm);
  float* TAB = (float*)(sm + OFF_TAB);
  const int t = threadIdx.x, w = t>>5, lane = t&31;

  // ---- one-time staging ----
  for (int e = t; e < 8448; e += NTH)
    ((uint4*)(sm+OFF_B))[e] = ((const uint4*)g_B)[e];
  for (int e = t; e < 2304; e += NTH) TAB[T_RELB + e] = g_relb[e];
  if (t < 128){
    TAB[T_W2D+t] = dW2[t]; TAB[T_W2R+t] = rW2[t]; TAB[T_BO+t] = g_bo[t];
    TAB[T_LN2G+t] = ln2g[t]; TAB[T_LN2B+t] = ln2b[t];
  }
  const float db2v = db2[0], rb2v = rb2[0];
  const float gamv = gam[0], lamv = lam[0], biav = bia[0];

  // fragment invariants
  const uint32_t aAddr = smb + ((16*w + (lane&15))*AST + ((lane>>4)<<3))*2;
  const uint32_t bAddr = smb + OFF_B + ((((lane>>4)<<3)+(lane&7))*AST + (((lane>>3)&1)<<3))*2;
  const int r0 = 16*w + (lane>>2), r1 = r0 + 8;
  const int n0 = r0 - 9*((r0*7282)>>16), n1 = r1 - 9*((r1*7282)>>16);
  const int jb = (lane&3)<<1;
  __syncthreads();

  for (int tile = blockIdx.x; tile < NTILES; tile += GRID){
    const int l0 = tile * TP;

    // ---- gather A: scrambled nbhd (k<128) via LDG.64, center (k>=128) via uint4 ----
    for (int e = t; e < 4608; e += NTH){
      int ch4 = e & 31, ps = e >> 5;
      int p = (ps*7282)>>16, s = ps - 9*p;
      int l = l0 + p;
      int h = (l>>7)&127, wq = l&127;
      int s3 = (s*11)>>5;
      int dh = s3 - 1, dw = (s - 3*s3) - 1;
      unsigned long long v = 0ull;
      if ((unsigned)(h+dh) < 128u && (unsigned)(wq+dw) < 128u)
        v = *(const unsigned long long*)(g_normbf + (((size_t)l + (dh<<7) + dw)<<7) + ch4*4);
      #pragma unroll
      for (int i = 0; i < 4; ++i){
        int q = (ch4*4 + i)*9 + s;
        int m = p*9 + (q>>7);
        *(uint16_t*)(sm + (m*AST + (q&127))*2) = (uint16_t)(v >> (16*i));
      }
    }
    for (int e = t; e < 2304; e += NTH){
      int m = e >> 4, c4 = e & 15;
      int p = (m*7282)>>16;
      *(uint4*)(sm + (m*AST + 128)*2 + c4*16) =
        *(const uint4*)(g_normbf + ((size_t)(l0+p)<<7) + c4*8);
    }
    __syncthreads();

    // ---- one MMA pass: M=144, N=256 (drive|res), K=256 ----
    float d[32][4];
    #pragma unroll
    for (int nt = 0; nt < 32; ++nt){ d[nt][0]=0.f; d[nt][1]=0.f; d[nt][2]=0.f; d[nt][3]=0.f; }
    #pragma unroll
    for (int kb = 0; kb < 16; ++kb){
      uint32_t a0,a1,a2,a3;
      ldm4(a0,a1,a2,a3, aAddr + kb*32);
      #pragma unroll
      for (int jt = 0; jt < 16; ++jt){
        uint32_t b0,b1,b2,b3;
        ldm4(b0,b1,b2,b3, bAddr + jt*8448 + kb*32);
        mma16816(d[2*jt],   a0,a1,a2,a3, b0,b1);
        mma16816(d[2*jt+1], a0,a1,a2,a3, b2,b3);
      }
    }

    // ---- epilogue: GELU * W2, per-lane then quad reduce ----
    {
      const float* rbd0 = TAB + T_RELB + n0*128;
      const float* rbd1 = TAB + T_RELB + n1*128;
      const float* rbr0 = TAB + T_RELB + 1152 + n0*128;
      const float* rbr1 = TAB + T_RELB + 1152 + n1*128;
      const float* w2d = TAB + T_W2D;
      const float* w2r = TAB + T_W2R;
      float a0d=0.f, a1d=0.f, a0r=0.f, a1r=0.f;
      #pragma unroll
      for (int nt = 0; nt < 16; ++nt){
        int j = nt*8 + jb;
        a0d += gelu(d[nt][0]+rbd0[j])*w2d[j] + gelu(d[nt][1]+rbd0[j+1])*w2d[j+1];
        a1d += gelu(d[nt][2]+rbd1[j])*w2d[j] + gelu(d[nt][3]+rbd1[j+1])*w2d[j+1];
        a0r += gelu(d[nt+16][0]+rbr0[j])*w2r[j] + gelu(d[nt+16][1]+rbr0[j+1])*w2r[j+1];
        a1r += gelu(d[nt+16][2]+rbr1[j])*w2r[j] + gelu(d[nt+16][3]+rbr1[j+1])*w2r[j+1];
      }
      a0d += __shfl_xor_sync(~0u,a0d,1); a0d += __shfl_xor_sync(~0u,a0d,2);
      a1d += __shfl_xor_sync(~0u,a1d,1); a1d += __shfl_xor_sync(~0u,a1d,2);
      a0r += __shfl_xor_sync(~0u,a0r,1); a0r += __shfl_xor_sync(~0u,a0r,2);
      a1r += __shfl_xor_sync(~0u,a1r,1); a1r += __shfl_xor_sync(~0u,a1r,2);
      if ((lane&3) == 0){
        TAB[T_DRV+r0] = a0d; TAB[T_DRV+r1] = a1d;
        TAB[T_RES+r0] = a0r; TAB[T_RES+r1] = a1r;
      }
    }
    __syncthreads();

    // ---- gate ----
    if (t < ROWS){
      float dv = TAB[T_DRV+t] + db2v, rv = TAB[T_RES+t] + rb2v;
      float sp = (rv > 20.f) ? rv : log1pf(expf(rv));
      float e = (gamv*dv) / (lamv*sp + 1e-6f) + biav;
      e = fminf(3.f, fmaxf(-3.f, e));
      TAB[T_GAT+t] = 1.f / (1.f + expf(-e));
    }
    __syncthreads();

    // ---- gsum + wsum accumulate (reads scrambled A from smem) ----
    if (t < TP){
      float s = 0.f;
      #pragma unroll
      for (int n = 0; n < 9; ++n) s += TAB[T_GAT + t*9 + n];
      TAB[T_GSM+t] = s;
    }
    float wacc[8];
    #pragma unroll
    for (int i = 0; i < 8; ++i){
      int e = t + i*NTH;
      if (e < 2048){
        int p = e>>7, c = e&127;
        const __nv_bfloat16* Ar = (const __nv_bfloat16*)sm + p*9*AST + c;
        const float* gt = TAB + T_GAT + p*9;
        float s = 0.f;
        #pragma unroll
        for (int n = 0; n < 9; ++n) s += gt[n] * __bfloat162float(Ar[n*AST]);
        wacc[i] = s;
      }
    }
    __syncthreads();
    #pragma unroll
    for (int i = 0; i < 8; ++i){
      int e = t + i*NTH;
      if (e < 2048) ((float*)sm)[(e>>7)*132 + (e&127)] = wacc[i];
    }
    __syncthreads();

    // ---- projection: wsum @ Wvo (Wvo streamed from L2 once) ----
    if (t < 256){
      int o = t & 127, half = t >> 7;
      const float* WV = g_Wvo + half*64*128 + o;
      const float* WS = (const float*)sm;
      float acc[16];
      #pragma unroll
      for (int p = 0; p < 16; ++p) acc[p] = 0.f;
      for (int cc = 0; cc < 64; cc += 4){
        int c = half*64 + cc;
        float w0 = WV[cc*128], w1 = WV[(cc+1)*128];
        float w2v = WV[(cc+2)*128], w3 = WV[(cc+3)*128];
        #pragma unroll
        for (int p = 0; p < 16; ++p){
          float4 ws = *(const float4*)(WS + p*132 + c);
          acc[p] += ws.x*w0 + ws.y*w1 + ws.z*w2v + ws.w*w3;
        }
      }
      float* P = (float*)(sm + 16384) + half*2048 + o;
      #pragma unroll
      for (int p = 0; p < 16; ++p) P[p*128] = acc[p];
    }
    __syncthreads();

    // ---- residual + LN2 + store (warp per position) ----
    for (int p = w; p < TP; p += 9){
      int l = l0 + p;
      float invgs = 1.f / fmaxf(TAB[T_GSM+p], 1e-6f);
      float4 ph0 = ((const float4*)(sm + 16384))[p*32 + lane];
      float4 ph1 = ((const float4*)(sm + 16384 + 8192))[p*32 + lane];
      float4 tk  = ((const float4*)tokens)[(size_t)l*32 + lane];
      float4 bov = ((const float4*)(TAB + T_BO))[lane];
      float u0 = tk.x + (ph0.x+ph1.x)*invgs + bov.x;
      float u1 = tk.y + (ph0.y+ph1.y)*invgs + bov.y;
      float u2 = tk.z + (ph0.z+ph1.z)*invgs + bov.z;
      float u3 = tk.w + (ph0.w+ph1.w)*invgs + bov.w;
      float ss = u0+u1+u2+u3, sq = u0*u0+u1*u1+u2*u2+u3*u3;
      #pragma unroll
      for (int o=16;o;o>>=1){ ss += __shfl_xor_sync(~0u,ss,o); sq += __shfl_xor_sync(~0u,sq,o); }
      float mean = ss*(1.f/128.f);
      float rs = rsqrtf(sq*(1.f/128.f) - mean*mean + 1e-5f);
      float4 gg = ((const float4*)(TAB+T_LN2G))[lane];
      float4 bb = ((const float4*)(TAB+T_LN2B))[lane];
      ((float4*)out)[(size_t)l*32 + lane] = make_float4(
        (u0-mean)*rs*gg.x+bb.x, (u1-mean)*rs*gg.y+bb.y,
        (u2-mean)*rs*gg.z+bb.z, (u3-mean)*rs*gg.w+bb.w);
    }
    __syncthreads();
  }
}

extern "C" void kernel_launch(void* const* d_in, const int* in_sizes, int n_in,
                              void* d_out, int out_size)
{
  const float* tokens = (const float*)d_in[0];
  const float* ln1g = (const float*)d_in[1];
  const float* ln1b = (const float*)d_in[2];
  const float* ln2g = (const float*)d_in[3];
  const float* ln2b = (const float*)d_in[4];
  const float* rel  = (const float*)d_in[5];
  const float* dW1  = (const float*)d_in[6];
  const float* db1  = (const float*)d_in[7];
  const float* dW2  = (const float*)d_in[8];
  const float* db2  = (const float*)d_in[9];
  const float* rW1  = (const float*)d_in[10];
  const float* rb1  = (const float*)d_in[11];
  const float* rW2  = (const float*)d_in[12];
  const float* rb2  = (const float*)d_in[13];
  const float* vW   = (const float*)d_in[14];
  const float* vb   = (const float*)d_in[15];
  const float* oW   = (const float*)d_in[16];
  const float* ob   = (const float*)d_in[17];
  const float* gam  = (const float*)d_in[18];
  const float* lam  = (const float*)d_in[19];
  const float* bia  = (const float*)d_in[20];

  cudaFuncSetAttribute(eml_main, cudaFuncAttributeMaxDynamicSharedMemorySize, SMEM_TOTAL);
  prep_kernel<<<(84352 + 255)/256, 256>>>(dW1, rW1, vW, oW, vb, ob, rel, db1, rb1);
  ln1_kernel<<<TOTP/16, 512>>>(tokens, ln1g, ln1b);
  eml_main<<<GRID, NTH, SMEM_TOTAL>>>(tokens, dW2, db2, rW2, rb2,
                                      ln2g, ln2b, gam, lam, bia, (float*)d_out);
}

// round 17
// speedup vs baseline: 3.9695x; 1.3129x over previous
#include <cuda_runtime.h>
#include <cuda_bf16.h>
#include <math.h>
#include <stdint.h>

#define TOTP 32768
#define TP 14
#define NTILES ((TOTP + TP - 1) / TP)   // 2341
#define GRID 148
#define NTH 256                          // 8 warps, 2/SMSP
#define ROWS 126
#define AST 264
#define OFF_B 67584                      // A: 128*264*2
#define OFF_TAB 202752                   // B: 256*264*2 = 135168
#define T_RELB 0
#define T_W2D 2304
#define T_W2R 2432
#define T_BO 2560
#define T_LN2G 2688
#define T_LN2B 2816
#define T_GAT 2944
#define T_GSM 3072
#define T_WSUM 3088                      // 14*132
#define SMEM_TOTAL (OFF_TAB + 4936*4)    // 222496

typedef unsigned long long u64;

__device__ __align__(16) __nv_bfloat16 g_normbf[(size_t)TOTP*128];
__device__ __align__(16) __nv_bfloat16 g_B[256*AST];
__device__ __align__(16) float g_Wvo[128*128];
__device__ float g_bo[128];
__device__ float g_relb[2304];

__device__ __forceinline__ uint32_t smem_u32(const void* p){
  uint32_t a;
  asm("{ .reg .u64 t; cvta.to.shared.u64 t, %1; cvt.u32.u64 %0, t; }" : "=r"(a) : "l"(p));
  return a;
}
__device__ __forceinline__ void ldm4(uint32_t& r0, uint32_t& r1, uint32_t& r2, uint32_t& r3, uint32_t a){
  asm volatile("ldmatrix.sync.aligned.m8n8.x4.shared.b16 {%0,%1,%2,%3}, [%4];"
               : "=r"(r0), "=r"(r1), "=r"(r2), "=r"(r3) : "r"(a));
}
__device__ __forceinline__ void mma16816(float* d, uint32_t a0, uint32_t a1, uint32_t a2, uint32_t a3,
                                         uint32_t b0, uint32_t b1){
  asm volatile("mma.sync.aligned.m16n8k16.row.col.f32.bf16.bf16.f32 "
               "{%0,%1,%2,%3},{%4,%5,%6,%7},{%8,%9},{%0,%1,%2,%3};"
               : "+f"(d[0]), "+f"(d[1]), "+f"(d[2]), "+f"(d[3])
               : "r"(a0), "r"(a1), "r"(a2), "r"(a3), "r"(b0), "r"(b1));
}
__device__ __forceinline__ u64 fma2(u64 a, u64 b, u64 c){
  u64 d;
  asm("fma.rn.f32x2 %0, %1, %2, %3;" : "=l"(d) : "l"(a), "l"(b), "l"(c));
  return d;
}
__device__ __forceinline__ u64 packf2(float x, float y){
  union { u64 u; float2 f; } cv; cv.f.x = x; cv.f.y = y; return cv.u;
}
__device__ __forceinline__ float pairsum(u64 v){
  union { u64 u; float2 f; } cv; cv.u = v; return cv.f.x + cv.f.y;
}
// fast gelu: A&S 7.1.26 erf, |err| <= 1.5e-7
__device__ __forceinline__ float gelu(float x){
  float ax = fabsf(x) * 0.70710678118654752f;
  float t  = __fdividef(1.f, fmaf(0.3275911f, ax, 1.f));
  float p  = t * fmaf(t, fmaf(t, fmaf(t, fmaf(t, 1.061405429f, -1.453152027f),
                    1.421413741f), -0.284496736f), 0.254829592f);
  float er = copysignf(fmaf(-p, __expf(-ax*ax), 1.f), x);
  return 0.5f * x * (1.f + er);
}

// ---------------- prep ----------------
__global__ void prep_kernel(const float* __restrict__ dW1, const float* __restrict__ rW1,
                            const float* __restrict__ vW,  const float* __restrict__ oW,
                            const float* __restrict__ vb,  const float* __restrict__ ob,
                            const float* __restrict__ rel,
                            const float* __restrict__ db1, const float* __restrict__ rb1)
{
  int idx = blockIdx.x*256 + threadIdx.x;
  if (idx < 65536){
    int j = idx >> 8, k = idx & 255;
    const float* W = (j < 128) ? dW1 : rW1;
    int jc = j & 127;
    float v = (k < 128) ? (W[(128+k)*128+jc] - W[(256+k)*128+jc])
                        : (W[(k-128)*128+jc] + W[(k+128)*128+jc]);
    g_B[j*AST+k] = __float2bfloat16(v);
    return;
  }
  idx -= 65536;
  if (idx < 2304){
    int wh = idx/1152, r = idx - wh*1152, n = r>>7, j = r&127;
    const float* W1 = wh ? rW1 : dW1;
    float a = (wh ? rb1 : db1)[j];
    #pragma unroll
    for (int p = 0; p < 8; ++p) a += rel[n*8+p] * W1[(384+p)*128+j];
    g_relb[idx] = a;
    return;
  }
  idx -= 2304;
  if (idx < 16384){
    int c = idx >> 7, o = idx & 127;
    float s = 0.f;
    for (int d = 0; d < 128; ++d) s += vW[c*128+d] * oW[d*128+o];
    g_Wvo[idx] = s;
    return;
  }
  idx -= 16384;
  if (idx < 128){
    float s = ob[idx];
    for (int d = 0; d < 128; ++d) s += vb[d] * oW[d*128+idx];
    g_bo[idx] = s;
  }
}

// ---------------- LN1 -> bf16 ----------------
__global__ void ln1_kernel(const float* __restrict__ tok, const float* __restrict__ g,
                           const float* __restrict__ b)
{
  int warp = (blockIdx.x*blockDim.x + threadIdx.x) >> 5, lane = threadIdx.x & 31;
  if (warp >= TOTP) return;
  float4 v = ((const float4*)(tok + (size_t)warp*128))[lane];
  float s = v.x+v.y+v.z+v.w;
  #pragma unroll
  for (int o=16;o;o>>=1) s += __shfl_xor_sync(~0u, s, o);
  float mean = s*(1.f/128.f);
  float dx=v.x-mean, dy=v.y-mean, dz=v.z-mean, dw=v.w-mean;
  float q = dx*dx+dy*dy+dz*dz+dw*dw;
  #pragma unroll
  for (int o=16;o;o>>=1) q += __shfl_xor_sync(~0u, q, o);
  float rs = rsqrtf(q*(1.f/128.f) + 1e-5f);
  float4 gg = ((const float4*)g)[lane], bb = ((const float4*)b)[lane];
  __nv_bfloat162 lo = __floats2bfloat162_rn(dx*rs*gg.x+bb.x, dy*rs*gg.y+bb.y);
  __nv_bfloat162 hi = __floats2bfloat162_rn(dz*rs*gg.z+bb.z, dw*rs*gg.w+bb.w);
  uint2 pk; pk.x = *(uint32_t*)&lo; pk.y = *(uint32_t*)&hi;
  ((uint2*)(g_normbf + (size_t)warp*128))[lane] = pk;
}

// ---------------- main (persistent) ----------------
__global__ void __launch_bounds__(NTH,1) eml_main(
    const float* __restrict__ tokens, const float* __restrict__ dW2,
    const float* __restrict__ db2, const float* __restrict__ rW2,
    const float* __restrict__ rb2, const float* __restrict__ ln2g,
    const float* __restrict__ ln2b, const float* __restrict__ gam,
    const float* __restrict__ lam, const float* __restrict__ bia,
    float* __restrict__ out)
{
  extern __shared__ __align__(16) unsigned char sm[];
  const uint32_t smb = smem_u32(sm);
  float* TAB = (float*)(sm + OFF_TAB);
  const int t = threadIdx.x, w = t>>5, lane = t&31;

  // one-time staging
  for (int e = t; e < 8448; e += NTH)
    ((uint4*)(sm+OFF_B))[e] = ((const uint4*)g_B)[e];
  for (int e = t; e < 2304; e += NTH) TAB[T_RELB + e] = g_relb[e];
  if (t < 128){
    TAB[T_W2D+t] = dW2[t]; TAB[T_W2R+t] = rW2[t]; TAB[T_BO+t] = g_bo[t];
    TAB[T_LN2G+t] = ln2g[t]; TAB[T_LN2B+t] = ln2b[t];
  }
  if (t < 66){  // zero A pad rows 126,127 (never rewritten)
    uint4 z = make_uint4(0,0,0,0);
    ((uint4*)(sm + 126*AST*2))[t] = z;
  }
  const float db2v = db2[0], rb2v = rb2[0];
  const float gamv = gam[0], lamv = lam[0], biav = bia[0];

  const uint32_t aAddr = smb + ((16*w + (lane&15))*AST + ((lane>>4)<<3))*2;
  const uint32_t bAddr = smb + OFF_B + ((((lane>>4)<<3)+(lane&7))*AST + (((lane>>3)&1)<<3))*2;
  const int r0 = 16*w + (lane>>2), r1 = r0 + 8;
  const int n0 = r0 - 9*((r0*7282)>>16), n1 = r1 - 9*((r1*7282)>>16);
  const int jb = (lane&3)<<1;
  __syncthreads();

  for (int tile = blockIdx.x; tile < NTILES; tile += GRID){
    const int l0 = tile * TP;

    // ---- gather A ----
    #pragma unroll 4
    for (int e = t; e < 4032; e += NTH){
      int ch4 = e & 31, ps = e >> 5;
      int p = (ps*7282)>>16, s = ps - 9*p;
      int l = l0 + p; if (l >= TOTP) l = TOTP-1;
      int h = (l>>7)&127, wq = l&127;
      int s3 = (s*11)>>5;
      int dh = s3 - 1, dw = (s - 3*s3) - 1;
      u64 v = 0ull;
      if ((unsigned)(h+dh) < 128u && (unsigned)(wq+dw) < 128u)
        v = *(const u64*)(g_normbf + (((size_t)l + (dh<<7) + dw)<<7) + ch4*4);
      #pragma unroll
      for (int i = 0; i < 4; ++i){
        int q = (ch4*4 + i)*9 + s;
        int m = p*9 + (q>>7);
        *(uint16_t*)(sm + (m*AST + (q&127))*2) = (uint16_t)(v >> (16*i));
      }
    }
    #pragma unroll 2
    for (int e = t; e < 2016; e += NTH){
      int m = e >> 4, c4 = e & 15;
      int p = (m*7282)>>16;
      int l = l0 + p; if (l >= TOTP) l = TOTP-1;
      *(uint4*)(sm + (m*AST + 128)*2 + c4*16) =
        *(const uint4*)(g_normbf + ((size_t)l<<7) + c4*8);
    }
    __syncthreads();

    // ---- MMA: M=128, N=256 (drive|res), K=256 ----
    float d[32][4];
    #pragma unroll
    for (int nt = 0; nt < 32; ++nt){ d[nt][0]=0.f; d[nt][1]=0.f; d[nt][2]=0.f; d[nt][3]=0.f; }
    #pragma unroll
    for (int kb = 0; kb < 16; ++kb){
      uint32_t a0,a1,a2,a3;
      ldm4(a0,a1,a2,a3, aAddr + kb*32);
      #pragma unroll
      for (int jt = 0; jt < 16; ++jt){
        uint32_t b0,b1,b2,b3;
        ldm4(b0,b1,b2,b3, bAddr + jt*8448 + kb*32);
        mma16816(d[2*jt],   a0,a1,a2,a3, b0,b1);
        mma16816(d[2*jt+1], a0,a1,a2,a3, b2,b3);
      }
    }

    // ---- epilogue + fused gate ----
    {
      const float* rbd0 = TAB + T_RELB + n0*128;
      const float* rbd1 = TAB + T_RELB + n1*128;
      const float* rbr0 = TAB + T_RELB + 1152 + n0*128;
      const float* rbr1 = TAB + T_RELB + 1152 + n1*128;
      const float* w2d = TAB + T_W2D;
      const float* w2r = TAB + T_W2R;
      float a0d=0.f, a1d=0.f, a0r=0.f, a1r=0.f;
      #pragma unroll
      for (int nt = 0; nt < 16; ++nt){
        int j = nt*8 + jb;
        a0d += gelu(d[nt][0]+rbd0[j])*w2d[j] + gelu(d[nt][1]+rbd0[j+1])*w2d[j+1];
        a1d += gelu(d[nt][2]+rbd1[j])*w2d[j] + gelu(d[nt][3]+rbd1[j+1])*w2d[j+1];
        a0r += gelu(d[nt+16][0]+rbr0[j])*w2r[j] + gelu(d[nt+16][1]+rbr0[j+1])*w2r[j+1];
        a1r += gelu(d[nt+16][2]+rbr1[j])*w2r[j] + gelu(d[nt+16][3]+rbr1[j+1])*w2r[j+1];
      }
      a0d += __shfl_xor_sync(~0u,a0d,1); a0d += __shfl_xor_sync(~0u,a0d,2);
      a1d += __shfl_xor_sync(~0u,a1d,1); a1d += __shfl_xor_sync(~0u,a1d,2);
      a0r += __shfl_xor_sync(~0u,a0r,1); a0r += __shfl_xor_sync(~0u,a0r,2);
      a1r += __shfl_xor_sync(~0u,a1r,1); a1r += __shfl_xor_sync(~0u,a1r,2);
      if ((lane&3) == 0){
        float dv0 = a0d + db2v, rv0 = a0r + rb2v;
        float dv1 = a1d + db2v, rv1 = a1r + rb2v;
        float sp0 = (rv0 > 20.f) ? rv0 : log1pf(__expf(rv0));
        float sp1 = (rv1 > 20.f) ? rv1 : log1pf(__expf(rv1));
        float e0 = fminf(3.f, fmaxf(-3.f, __fdividef(gamv*dv0, fmaf(lamv, sp0, 1e-6f)) + biav));
        float e1 = fminf(3.f, fmaxf(-3.f, __fdividef(gamv*dv1, fmaf(lamv, sp1, 1e-6f)) + biav));
        TAB[T_GAT+r0] = __fdividef(1.f, 1.f + __expf(-e0));
        TAB[T_GAT+r1] = __fdividef(1.f, 1.f + __expf(-e1));
      }
    }
    __syncthreads();

    // ---- gsum + wsum (to TAB, no extra sync) ----
    if (t < TP){
      float s = 0.f;
      #pragma unroll
      for (int n = 0; n < 9; ++n) s += TAB[T_GAT + t*9 + n];
      TAB[T_GSM+t] = s;
    }
    #pragma unroll
    for (int i = 0; i < 7; ++i){
      int e = t + i*NTH;
      int p = e>>7, c = e&127;
      const __nv_bfloat16* Ar = (const __nv_bfloat16*)sm + p*9*AST + c;
      const float* gt = TAB + T_GAT + p*9;
      float s = 0.f;
      #pragma unroll
      for (int n = 0; n < 9; ++n) s += gt[n] * __bfloat162float(Ar[n*AST]);
      TAB[T_WSUM + p*132 + c] = s;
    }
    __syncthreads();

    // ---- projection: wsum @ Wvo, f32x2 packed, w ping-pong ----
    {
      const int o = t & 127, half = t >> 7;
      const float* WV = g_Wvo + half*8192 + o;
      const float* WS = TAB + T_WSUM + half*64;
      u64 acc2[TP];
      #pragma unroll
      for (int p = 0; p < TP; ++p) acc2[p] = 0ull;
      float w0 = WV[0], w1 = WV[128], w2v = WV[256], w3 = WV[384];
      #pragma unroll
      for (int cc = 0; cc < 64; cc += 4){
        float nw0=0.f, nw1=0.f, nw2=0.f, nw3=0.f;
        if (cc < 60){
          nw0 = WV[(cc+4)*128]; nw1 = WV[(cc+5)*128];
          nw2 = WV[(cc+6)*128]; nw3 = WV[(cc+7)*128];
        }
        u64 wp01 = packf2(w0, w1), wp23 = packf2(w2v, w3);
        #pragma unroll
        for (int p = 0; p < TP; ++p){
          u64 ws01 = *(const u64*)(WS + p*132 + cc);
          u64 ws23 = *(const u64*)(WS + p*132 + cc + 2);
          acc2[p] = fma2(ws01, wp01, acc2[p]);
          acc2[p] = fma2(ws23, wp23, acc2[p]);
        }
        w0 = nw0; w1 = nw1; w2v = nw2; w3 = nw3;
      }
      float* P = (float*)sm + half*1792 + o;
      #pragma unroll
      for (int p = 0; p < TP; ++p) P[p*128] = pairsum(acc2[p]);
    }
    __syncthreads();

    // ---- residual + LN2 + store ----
    for (int p = w; p < TP; p += 8){
      int l = l0 + p;
      if (l >= TOTP) continue;
      float invgs = __fdividef(1.f, fmaxf(TAB[T_GSM+p], 1e-6f));
      float4 ph0 = ((const float4*)sm)[p*32 + lane];
      float4 ph1 = ((const float4*)(sm + 7168))[p*32 + lane];
      float4 tk  = ((const float4*)tokens)[(size_t)l*32 + lane];
      float4 bov = ((const float4*)(TAB + T_BO))[lane];
      float u0 = tk.x + (ph0.x+ph1.x)*invgs + bov.x;
      float u1 = tk.y + (ph0.y+ph1.y)*invgs + bov.y;
      float u2 = tk.z + (ph0.z+ph1.z)*invgs + bov.z;
      float u3 = tk.w + (ph0.w+ph1.w)*invgs + bov.w;
      float ss = u0+u1+u2+u3, sq = u0*u0+u1*u1+u2*u2+u3*u3;
      #pragma unroll
      for (int o=16;o;o>>=1){ ss += __shfl_xor_sync(~0u,ss,o); sq += __shfl_xor_sync(~0u,sq,o); }
      float mean = ss*(1.f/128.f);
      float rs = rsqrtf(sq*(1.f/128.f) - mean*mean + 1e-5f);
      float4 gg = ((const float4*)(TAB+T_LN2G))[lane];
      float4 bb = ((const float4*)(TAB+T_LN2B))[lane];
      ((float4*)out)[(size_t)l*32 + lane] = make_float4(
        (u0-mean)*rs*gg.x+bb.x, (u1-mean)*rs*gg.y+bb.y,
        (u2-mean)*rs*gg.z+bb.z, (u3-mean)*rs*gg.w+bb.w);
    }
    __syncthreads();
  }
}

extern "C" void kernel_launch(void* const* d_in, const int* in_sizes, int n_in,
                              void* d_out, int out_size)
{
  const float* tokens = (const float*)d_in[0];
  const float* ln1g = (const float*)d_in[1];
  const float* ln1b = (const float*)d_in[2];
  const float* ln2g = (const float*)d_in[3];
  const float* ln2b = (const float*)d_in[4];
  const float* rel  = (const float*)d_in[5];
  const float* dW1  = (const float*)d_in[6];
  const float* db1  = (const float*)d_in[7];
  const float* dW2  = (const float*)d_in[8];
  const float* db2  = (const float*)d_in[9];
  const float* rW1  = (const float*)d_in[10];
  const float* rb1  = (const float*)d_in[11];
  const float* rW2  = (const float*)d_in[12];
  const float* rb2  = (const float*)d_in[13];
  const float* vW   = (const float*)d_in[14];
  const float* vb   = (const float*)d_in[15];
  const float* oW   = (const float*)d_in[16];
  const float* ob   = (const float*)d_in[17];
  const float* gam  = (const float*)d_in[18];
  const float* lam  = (const float*)d_in[19];
  const float* bia  = (const float*)d_in[20];

  cudaFuncSetAttribute(eml_main, cudaFuncAttributeMaxDynamicSharedMemorySize, SMEM_TOTAL);
  prep_kernel<<<(84352 + 255)/256, 256>>>(dW1, rW1, vW, oW, vb, ob, rel, db1, rb1);
  ln1_kernel<<<TOTP/16, 512>>>(tokens, ln1g, ln1b);
  eml_main<<<GRID, NTH, SMEM_TOTAL>>>(tokens, dW2, db2, rW2, rb2,
                                      ln2g, ln2b, gam, lam, bia, (float*)d_out);
}